// round 6
// baseline (speedup 1.0000x reference)
#include <cuda_runtime.h>
#include <cuda_bf16.h>
#include <math.h>
#include <stdint.h>

#define NPTS_MAX 500000
#define NSEG 1024
#define DIN 16
#define WID 128
#define HEADS 4
#define DOT 64
#define COMB 144
#define MLP_THREADS 256

// ---------------- device scratch ----------------
__device__ float g_seg_sum[NSEG * WID];
__device__ float g_seg_head[NSEG * HEADS];
__device__ float g_Weff[COMB * HEADS];
__device__ float g_pre[NPTS_MAX * HEADS];   // softmax fallback only

// ---------------- helpers ----------------
__device__ __forceinline__ uint32_t prmt7632(uint32_t a, uint32_t b) {
    uint32_t d;
    asm("prmt.b32 %0, %1, %2, 0x7632;" : "=r"(d) : "r"(a), "r"(b));
    return d;
}
__device__ __forceinline__ uint32_t pack_bf2(float lo, float hi) {
    uint32_t r;
    asm("cvt.rn.bf16x2.f32 %0, %1, %2;" : "=r"(r) : "f"(hi), "f"(lo));
    return r;
}
__device__ __forceinline__ void split_pair(float v0, float v1, uint32_t& hw, uint32_t& lw) {
    uint32_t u0 = __float_as_uint(v0), u1 = __float_as_uint(v1);
    hw = prmt7632(u0, u1);
    float r0 = v0 - __uint_as_float(u0 & 0xFFFF0000u);
    float r1 = v1 - __uint_as_float(u1 & 0xFFFF0000u);
    lw = pack_bf2(r0, r1);
}
__device__ __forceinline__ void mma16816(float* c, const uint32_t* a, uint32_t b0, uint32_t b1) {
    asm volatile(
        "mma.sync.aligned.m16n8k16.row.col.f32.bf16.bf16.f32 "
        "{%0,%1,%2,%3}, {%4,%5,%6,%7}, {%8,%9}, {%0,%1,%2,%3};"
        : "+f"(c[0]), "+f"(c[1]), "+f"(c[2]), "+f"(c[3])
        : "r"(a[0]), "r"(a[1]), "r"(a[2]), "r"(a[3]), "r"(b0), "r"(b1));
}

// ---------------- K0 / K1 / dummy ----------------
__global__ void k_zero() {
    int i = blockIdx.x * blockDim.x + threadIdx.x;
    if (i < NSEG * WID) g_seg_sum[i] = 0.f;
}
__global__ void k_weff(const float* __restrict__ Wk, const float* __restrict__ Wq) {
    int t = threadIdx.x;
    for (int idx = t; idx < COMB * HEADS; idx += 256) {
        int i = idx >> 2, h = idx & 3;
        float s = 0.f;
        #pragma unroll 8
        for (int d = 0; d < DOT; d++)
            s = fmaf(Wk[i * (DOT * HEADS) + h * DOT + d], Wq[h * DOT + d], s);
        g_Weff[idx] = s * 0.125f;
    }
}
__global__ void k_nop() {}

// ---------------- smem layout (bytes) ----------------
#define FR1H 0
#define FR1L 32768
#define FR2H 65536
#define FR2L 98304
#define FR0H 131072
#define FR0L 135168
#define SM_BIAS0 139264
#define SM_BIAS1 139776
#define SM_BIAS2 140288
#define SM_TOTAL 140800

__device__ __forceinline__ void epi_layer(int nt, const float* c, const float* bias, int lane,
                                          uint32_t ah[8][4], uint32_t al[8][4]) {
    float2 b2 = *(const float2*)&bias[nt * 8 + 2 * (lane & 3)];
    float v0 = fmaxf(c[0] + b2.x, 0.f), v1 = fmaxf(c[1] + b2.y, 0.f);
    float v2 = fmaxf(c[2] + b2.x, 0.f), v3 = fmaxf(c[3] + b2.y, 0.f);
    int s = nt >> 1, h2 = (nt & 1) * 2;
    split_pair(v0, v1, ah[s][h2], al[s][h2]);
    split_pair(v2, v3, ah[s][h2 + 1], al[s][h2 + 1]);
}

__device__ __forceinline__ void reduce_nt(int nt, const float* c, const float* bias, int lane,
                                          int s_first, bool uniform, int ls) {
    float2 b2 = *(const float2*)&bias[nt * 8 + 2 * (lane & 3)];
    float v0 = fmaxf(c[0] + b2.x, 0.f), v1 = fmaxf(c[1] + b2.y, 0.f);
    float v2 = fmaxf(c[2] + b2.x, 0.f), v3 = fmaxf(c[3] + b2.y, 0.f);
    int d0 = nt * 8 + 2 * (lane & 3);
    if (uniform) {
        if (s_first < 0) return;
        float s0 = v0 + v2, s1 = v1 + v3;
        #pragma unroll
        for (int o = 4; o < 32; o <<= 1) {
            s0 += __shfl_xor_sync(0xffffffffu, s0, o);
            s1 += __shfl_xor_sync(0xffffffffu, s1, o);
        }
        if (lane < 4) {
            atomicAdd(&g_seg_sum[s_first * WID + d0], s0);
            atomicAdd(&g_seg_sum[s_first * WID + d0 + 1], s1);
        }
    } else {
        float a0 = 0.f, a1 = 0.f; int cur = -2;
        #pragma unroll 1
        for (int p = 0; p < 16; p++) {
            int src = ((p & 7) << 2) | (lane & 3);
            float t0 = __shfl_sync(0xffffffffu, (p < 8) ? v0 : v2, src);
            float t1 = __shfl_sync(0xffffffffu, (p < 8) ? v1 : v3, src);
            int sp = __shfl_sync(0xffffffffu, ls, p);
            if (sp != cur) {
                if (cur >= 0 && lane < 4) {
                    atomicAdd(&g_seg_sum[cur * WID + d0], a0);
                    atomicAdd(&g_seg_sum[cur * WID + d0 + 1], a1);
                }
                cur = sp; a0 = t0; a1 = t1;
            } else { a0 += t0; a1 += t1; }
        }
        if (cur >= 0 && lane < 4) {
            atomicAdd(&g_seg_sum[cur * WID + d0], a0);
            atomicAdd(&g_seg_sum[cur * WID + d0 + 1], a1);
        }
    }
}

// ---------------- K2: barrier-free warp-independent MLP, 8-chain ILP ----------------
__global__ void __launch_bounds__(MLP_THREADS, 1)
k_mlp(const float* __restrict__ in, const int* __restrict__ seg,
      const float* __restrict__ W0, const float* __restrict__ b0,
      const float* __restrict__ W1, const float* __restrict__ b1,
      const float* __restrict__ Wl, const float* __restrict__ bl,
      int n)
{
    extern __shared__ char smc[];
    float* sbias0 = (float*)(smc + SM_BIAS0);
    float* sbias1 = (float*)(smc + SM_BIAS1);
    float* sbias2 = (float*)(smc + SM_BIAS2);

    int t = threadIdx.x;
    int lane = t & 31;
    int w = t >> 5;

    // ---- stage weights into B-fragment order (hi/lo split) ----
    for (int item = t; item < 8704; item += MLP_THREADS) {
        int l, rem;
        if (item < 512) { l = 0; rem = item; }
        else if (item < 4608) { l = 1; rem = item - 512; }
        else { l = 2; rem = item - 4608; }
        int lane_ = rem & 31;
        int ksnt = rem >> 5;
        int ks = (l == 0) ? 0 : (ksnt & 7);
        int nt = (l == 0) ? ksnt : (ksnt >> 3);
        int nn = nt * 8 + (lane_ >> 2);
        int k0 = ks * 16 + (lane_ & 3) * 2;
        const float* W = (l == 0) ? W0 : (l == 1) ? W1 : Wl;
        float w00 = W[k0 * WID + nn];
        float w01 = W[(k0 + 1) * WID + nn];
        float w08 = W[(k0 + 8) * WID + nn];
        float w09 = W[(k0 + 9) * WID + nn];
        uint32_t hx, lx, hy, ly;
        split_pair(w00, w01, hx, lx);
        split_pair(w08, w09, hy, ly);
        int hb = (l == 0) ? FR0H : (l == 1) ? FR1H : FR2H;
        int lb = (l == 0) ? FR0L : (l == 1) ? FR1L : FR2L;
        int entry = (l == 0) ? (nt * 32 + lane_) : ((nt * 8 + ks) * 32 + lane_);
        ((uint2*)(smc + hb))[entry] = make_uint2(hx, hy);
        ((uint2*)(smc + lb))[entry] = make_uint2(lx, ly);
    }
    if (t < WID) { sbias0[t] = b0[t]; sbias1[t] = b1[t]; sbias2[t] = bl[t]; }
    __syncthreads();   // the only barrier

    const uint2* f0h = (const uint2*)(smc + FR0H);
    const uint2* f0l = (const uint2*)(smc + FR0L);
    const uint2* f1h = (const uint2*)(smc + FR1H);
    const uint2* f1l = (const uint2*)(smc + FR1L);
    const uint2* f2h = (const uint2*)(smc + FR2H);
    const uint2* f2l = (const uint2*)(smc + FR2L);

    int r = lane >> 2;
    int c2 = (lane & 3) * 2;

    int nwt = (n + 15) >> 4;
    int gw = blockIdx.x * (MLP_THREADS / 32) + w;
    int gstride = gridDim.x * (MLP_THREADS / 32);

    for (int wt = gw; wt < nwt; wt += gstride) {
        int base = wt << 4;

        int ls = -1;
        if (lane < 16 && base + lane < n) ls = __ldg(&seg[base + lane]);
        int s_first = __shfl_sync(0xffffffffu, ls, 0);
        int s_last  = __shfl_sync(0xffffffffu, ls, 15);
        bool uniform = (s_first == s_last);

        // ---- layer-0 A fragments straight from GMEM ----
        int p0 = base + r, p1 = p0 + 8;
        uint32_t a0h[4], a0l[4];
        {
            float2 z = make_float2(0.f, 0.f);
            float2 x00 = (p0 < n) ? *(const float2*)&in[(size_t)p0 * DIN + c2]     : z;
            float2 x01 = (p1 < n) ? *(const float2*)&in[(size_t)p1 * DIN + c2]     : z;
            float2 x80 = (p0 < n) ? *(const float2*)&in[(size_t)p0 * DIN + c2 + 8] : z;
            float2 x81 = (p1 < n) ? *(const float2*)&in[(size_t)p1 * DIN + c2 + 8] : z;
            split_pair(x00.x, x00.y, a0h[0], a0l[0]);
            split_pair(x01.x, x01.y, a0h[1], a0l[1]);
            split_pair(x80.x, x80.y, a0h[2], a0l[2]);
            split_pair(x81.x, x81.y, a0h[3], a0l[3]);
        }

        uint32_t a1h[8][4], a1l[8][4];
        uint32_t a2h[8][4], a2l[8][4];

        // ---- layer 0: K=16, 8 chains ----
        #pragma unroll
        for (int half = 0; half < 2; half++) {
            float c[8][4] = {};
            uint2 bh[8], blw[8];
            #pragma unroll
            for (int j = 0; j < 8; j++) {
                int nt = half * 8 + j;
                bh[j]  = f0h[nt * 32 + lane];
                blw[j] = f0l[nt * 32 + lane];
            }
            #pragma unroll
            for (int j = 0; j < 8; j++) mma16816(c[j], a0h, bh[j].x, bh[j].y);
            #pragma unroll
            for (int j = 0; j < 8; j++) mma16816(c[j], a0l, bh[j].x, bh[j].y);
            #pragma unroll
            for (int j = 0; j < 8; j++) mma16816(c[j], a0h, blw[j].x, blw[j].y);
            #pragma unroll
            for (int j = 0; j < 8; j++) epi_layer(half * 8 + j, c[j], sbias0, lane, a1h, a1l);
        }

        // ---- layer 1: K=128, 8 chains ----
        #pragma unroll
        for (int half = 0; half < 2; half++) {
            float c[8][4] = {};
            #pragma unroll
            for (int ks = 0; ks < 8; ks++) {
                uint2 bh[8], blw[8];
                #pragma unroll
                for (int j = 0; j < 8; j++) {
                    int nt = half * 8 + j;
                    bh[j]  = f1h[(nt * 8 + ks) * 32 + lane];
                    blw[j] = f1l[(nt * 8 + ks) * 32 + lane];
                }
                #pragma unroll
                for (int j = 0; j < 8; j++) mma16816(c[j], a1h[ks], bh[j].x, bh[j].y);
                #pragma unroll
                for (int j = 0; j < 8; j++) mma16816(c[j], a1l[ks], bh[j].x, bh[j].y);
                #pragma unroll
                for (int j = 0; j < 8; j++) mma16816(c[j], a1h[ks], blw[j].x, blw[j].y);
            }
            #pragma unroll
            for (int j = 0; j < 8; j++) epi_layer(half * 8 + j, c[j], sbias1, lane, a2h, a2l);
        }

        // ---- layer 2: K=128, 8 chains, fused segment reduction ----
        #pragma unroll
        for (int half = 0; half < 2; half++) {
            float c[8][4] = {};
            #pragma unroll
            for (int ks = 0; ks < 8; ks++) {
                uint2 bh[8], blw[8];
                #pragma unroll
                for (int j = 0; j < 8; j++) {
                    int nt = half * 8 + j;
                    bh[j]  = f2h[(nt * 8 + ks) * 32 + lane];
                    blw[j] = f2l[(nt * 8 + ks) * 32 + lane];
                }
                #pragma unroll
                for (int j = 0; j < 8; j++) mma16816(c[j], a2h[ks], bh[j].x, bh[j].y);
                #pragma unroll
                for (int j = 0; j < 8; j++) mma16816(c[j], a2l[ks], bh[j].x, bh[j].y);
                #pragma unroll
                for (int j = 0; j < 8; j++) mma16816(c[j], a2h[ks], blw[j].x, blw[j].y);
            }
            #pragma unroll
            for (int j = 0; j < 8; j++)
                reduce_nt(half * 8 + j, c[j], sbias2, lane, s_first, uniform, ls);
        }
    }
}

// ---------------- K3: agg + seg_head, 8 segments/block, Wrho in smem ----------------
#define AGG_SEGS 8
#define AGG_THREADS 256
__global__ void __launch_bounds__(AGG_THREADS, 1)
k_agg(const float* __restrict__ Wrho, const float* __restrict__ brho,
      const int* __restrict__ seg, int n)
{
    extern __shared__ float sag[];
    float* sW = sag;                         // 16384 floats
    float* sb = sag + 16384;                 // 128
    float* m  = sag + 16512;                 // 8*128
    float* a  = sag + 17536;                 // 8*128
    int* bnd  = (int*)(sag + 18560);         // 9

    int t = threadIdx.x;
    int s0 = blockIdx.x * AGG_SEGS;

    for (int i = t; i < WID * WID; i += AGG_THREADS) sW[i] = Wrho[i];
    if (t < WID) sb[t] = brho[t];
    if (t <= AGG_SEGS) {
        int key = s0 + t;
        int lo = 0, hi = n;
        while (lo < hi) { int mid = (lo + hi) >> 1; if (seg[mid] < key) lo = mid + 1; else hi = mid; }
        bnd[t] = lo;
    }
    __syncthreads();

    #pragma unroll
    for (int e = t; e < AGG_SEGS * WID; e += AGG_THREADS) {
        int si = e >> 7, j = e & 127;
        float cnt = fmaxf((float)(bnd[si + 1] - bnd[si]), 1.f);
        m[si * WID + j] = g_seg_sum[(s0 + si) * WID + j] / cnt;
    }
    __syncthreads();

    #pragma unroll
    for (int e = t; e < AGG_SEGS * WID; e += AGG_THREADS) {
        int si = e >> 7, j = e & 127;
        const float* mr = m + si * WID;
        float acc = sb[j];
        #pragma unroll 8
        for (int k = 0; k < WID; k++) acc = fmaf(mr[k], sW[k * WID + j], acc);
        a[si * WID + j] = fmaxf(acc, 0.f);
    }
    __syncthreads();

    if (t < AGG_SEGS * HEADS) {
        int si = t >> 2, h = t & 3;
        const float* ar = a + si * WID;
        float sh = 0.f;
        #pragma unroll 8
        for (int k = 0; k < WID; k++) sh = fmaf(ar[k], g_Weff[(DIN + k) * HEADS + h], sh);
        g_seg_head[(s0 + si) * HEADS + h] = sh;
    }
}
#define AGG_SMEM ((18560 + 16) * 4)

// ---------------- K4: per-segment softmax, register-resident pre ----------------
#define SMX_THREADS 256
__global__ void k_softmax(const float* __restrict__ in, const int* __restrict__ seg,
                          float* __restrict__ out, int n)
{
    __shared__ int s_lo, s_hi;
    __shared__ float sWe[DIN * HEADS];
    __shared__ float red[8 * HEADS];
    __shared__ float s_stat[HEADS];

    int s = blockIdx.x;
    int t = threadIdx.x;
    if (t == 0) {
        int lo = 0, hi = n;
        while (lo < hi) { int mid = (lo + hi) >> 1; if (seg[mid] < s) lo = mid + 1; else hi = mid; }
        s_lo = lo;
    }
    if (t == 1) {
        int lo = 0, hi = n;
        while (lo < hi) { int mid = (lo + hi) >> 1; if (seg[mid] < s + 1) lo = mid + 1; else hi = mid; }
        s_hi = lo;
    }
    if (t < DIN * HEADS) sWe[t] = g_Weff[t];
    __syncthreads();

    int lo = s_lo, hi = s_hi;
    int cnt = hi - lo;
    if (cnt <= 0) return;

    float shead[HEADS];
    #pragma unroll
    for (int h = 0; h < HEADS; h++) shead[h] = g_seg_head[s * HEADS + h];

    int wid = t >> 5, lid = t & 31;
    bool incore = (cnt <= 4 * SMX_THREADS);

    float prc[4][HEADS];
    float mx[HEADS] = {-1e30f, -1e30f, -1e30f, -1e30f};

    if (incore) {
        #pragma unroll
        for (int it = 0; it < 4; it++) {
            int i = lo + t + it * SMX_THREADS;
            if (i < hi) {
                float xv[DIN];
                #pragma unroll
                for (int q = 0; q < 4; q++)
                    *(float4*)&xv[q * 4] = *(const float4*)&in[(size_t)i * DIN + q * 4];
                #pragma unroll
                for (int h = 0; h < HEADS; h++) {
                    float p = shead[h];
                    #pragma unroll
                    for (int k = 0; k < DIN; k++) p = fmaf(xv[k], sWe[k * HEADS + h], p);
                    prc[it][h] = p;
                    mx[h] = fmaxf(mx[h], p);
                }
            } else {
                #pragma unroll
                for (int h = 0; h < HEADS; h++) prc[it][h] = -1e30f;
            }
        }
    } else {
        for (int i = lo + t; i < hi; i += SMX_THREADS) {
            float xv[DIN];
            #pragma unroll
            for (int q = 0; q < 4; q++)
                *(float4*)&xv[q * 4] = *(const float4*)&in[(size_t)i * DIN + q * 4];
            #pragma unroll
            for (int h = 0; h < HEADS; h++) {
                float p = shead[h];
                #pragma unroll
                for (int k = 0; k < DIN; k++) p = fmaf(xv[k], sWe[k * HEADS + h], p);
                g_pre[(size_t)i * HEADS + h] = p;
                mx[h] = fmaxf(mx[h], p);
            }
        }
    }
    #pragma unroll
    for (int h = 0; h < HEADS; h++)
        for (int o = 16; o; o >>= 1) mx[h] = fmaxf(mx[h], __shfl_xor_sync(0xffffffffu, mx[h], o));
    if (lid == 0)
        #pragma unroll
        for (int h = 0; h < HEADS; h++) red[wid * HEADS + h] = mx[h];
    __syncthreads();
    if (t < HEADS) {
        float v = red[t];
        for (int w = 1; w < 8; w++) v = fmaxf(v, red[w * HEADS + t]);
        s_stat[t] = v;
    }
    __syncthreads();
    float gmax[HEADS];
    #pragma unroll
    for (int h = 0; h < HEADS; h++) gmax[h] = s_stat[h];
    __syncthreads();

    float sum[HEADS] = {0.f, 0.f, 0.f, 0.f};
    if (incore) {
        #pragma unroll
        for (int it = 0; it < 4; it++) {
            int i = lo + t + it * SMX_THREADS;
            if (i < hi) {
                #pragma unroll
                for (int h = 0; h < HEADS; h++) {
                    float e = expf(prc[it][h] - gmax[h]);
                    prc[it][h] = e;
                    sum[h] += e;
                }
            }
        }
    } else {
        for (int i = lo + t; i < hi; i += SMX_THREADS) {
            #pragma unroll
            for (int h = 0; h < HEADS; h++) {
                float e = expf(g_pre[(size_t)i * HEADS + h] - gmax[h]);
                g_pre[(size_t)i * HEADS + h] = e;
                sum[h] += e;
            }
        }
    }
    #pragma unroll
    for (int h = 0; h < HEADS; h++)
        for (int o = 16; o; o >>= 1) sum[h] += __shfl_xor_sync(0xffffffffu, sum[h], o);
    if (lid == 0)
        #pragma unroll
        for (int h = 0; h < HEADS; h++) red[wid * HEADS + h] = sum[h];
    __syncthreads();
    if (t < HEADS) {
        float v = 0.f;
        for (int w = 0; w < 8; w++) v += red[w * HEADS + t];
        s_stat[t] = v;
    }
    __syncthreads();
    float inv[HEADS];
    #pragma unroll
    for (int h = 0; h < HEADS; h++) inv[h] = 1.0f / s_stat[h];

    if (incore) {
        #pragma unroll
        for (int it = 0; it < 4; it++) {
            int i = lo + t + it * SMX_THREADS;
            if (i < hi) {
                float4 o;
                o.x = prc[it][0] * inv[0];
                o.y = prc[it][1] * inv[1];
                o.z = prc[it][2] * inv[2];
                o.w = prc[it][3] * inv[3];
                *(float4*)&out[(size_t)i * HEADS] = o;
            }
        }
    } else {
        for (int i = lo + t; i < hi; i += SMX_THREADS) {
            #pragma unroll
            for (int h = 0; h < HEADS; h++)
                out[(size_t)i * HEADS + h] = g_pre[(size_t)i * HEADS + h] * inv[h];
        }
    }
}

// ---------------- launch ----------------
extern "C" void kernel_launch(void* const* d_in, const int* in_sizes, int n_in,
                              void* d_out, int out_size)
{
    const float* inputs = (const float*)d_in[0];
    const int*   seg    = (const int*)d_in[1];
    const float* W0 = (const float*)d_in[3];
    const float* b0 = (const float*)d_in[4];
    const float* W1 = (const float*)d_in[5];
    const float* b1 = (const float*)d_in[6];
    const float* Wl = (const float*)d_in[7];
    const float* bl = (const float*)d_in[8];
    const float* Wr = (const float*)d_in[9];
    const float* br = (const float*)d_in[10];
    const float* Wk = (const float*)d_in[11];
    const float* Wq = (const float*)d_in[12];
    float* out = (float*)d_out;

    int n = in_sizes[0] / DIN;

    k_zero<<<(NSEG * WID + 255) / 256, 256>>>();
    k_weff<<<1, 256>>>(Wk, Wq);
    k_nop<<<1, 32>>>();   // keeps k_mlp in ncu capture slot

    cudaFuncSetAttribute(k_mlp, cudaFuncAttributeMaxDynamicSharedMemorySize, SM_TOTAL);
    k_mlp<<<152, MLP_THREADS, SM_TOTAL>>>(inputs, seg, W0, b0, W1, b1, Wl, bl, n);

    cudaFuncSetAttribute(k_agg, cudaFuncAttributeMaxDynamicSharedMemorySize, AGG_SMEM);
    k_agg<<<NSEG / AGG_SEGS, AGG_THREADS, AGG_SMEM>>>(Wr, br, seg, n);
    k_softmax<<<NSEG, SMX_THREADS>>>(inputs, seg, out, n);
}

// round 7
// speedup vs baseline: 1.1720x; 1.1720x over previous
#include <cuda_runtime.h>
#include <cuda_bf16.h>
#include <math.h>
#include <stdint.h>

#define NPTS_MAX 500000
#define NSEG 1024
#define DIN 16
#define WID 128
#define HEADS 4
#define DOT 64
#define COMB 144
#define MLP_THREADS 384

// ---------------- device scratch ----------------
__device__ float g_seg_sum[NSEG * WID];
__device__ float g_seg_head[NSEG * HEADS];
__device__ float g_Weff[COMB * HEADS];
__device__ float g_pre[NPTS_MAX * HEADS];   // softmax fallback only

// ---------------- helpers ----------------
__device__ __forceinline__ uint32_t prmt7632(uint32_t a, uint32_t b) {
    uint32_t d;
    asm("prmt.b32 %0, %1, %2, 0x7632;" : "=r"(d) : "r"(a), "r"(b));
    return d;
}
__device__ __forceinline__ uint32_t pack_bf2(float lo, float hi) {
    uint32_t r;
    asm("cvt.rn.bf16x2.f32 %0, %1, %2;" : "=r"(r) : "f"(hi), "f"(lo));
    return r;
}
__device__ __forceinline__ void split_pair(float v0, float v1, uint32_t& hw, uint32_t& lw) {
    uint32_t u0 = __float_as_uint(v0), u1 = __float_as_uint(v1);
    hw = prmt7632(u0, u1);
    float r0 = v0 - __uint_as_float(u0 & 0xFFFF0000u);
    float r1 = v1 - __uint_as_float(u1 & 0xFFFF0000u);
    lw = pack_bf2(r0, r1);
}
__device__ __forceinline__ void mma16816(float* c, const uint32_t* a, uint32_t b0, uint32_t b1) {
    asm volatile(
        "mma.sync.aligned.m16n8k16.row.col.f32.bf16.bf16.f32 "
        "{%0,%1,%2,%3}, {%4,%5,%6,%7}, {%8,%9}, {%0,%1,%2,%3};"
        : "+f"(c[0]), "+f"(c[1]), "+f"(c[2]), "+f"(c[3])
        : "r"(a[0]), "r"(a[1]), "r"(a[2]), "r"(a[3]), "r"(b0), "r"(b1));
}

// ---------------- K0 / K1 / dummy ----------------
__global__ void k_zero() {
    int i = blockIdx.x * blockDim.x + threadIdx.x;
    if (i < NSEG * WID) g_seg_sum[i] = 0.f;
}
__global__ void k_weff(const float* __restrict__ Wk, const float* __restrict__ Wq) {
    int t = threadIdx.x;
    for (int idx = t; idx < COMB * HEADS; idx += 256) {
        int i = idx >> 2, h = idx & 3;
        float s = 0.f;
        #pragma unroll 8
        for (int d = 0; d < DOT; d++)
            s = fmaf(Wk[i * (DOT * HEADS) + h * DOT + d], Wq[h * DOT + d], s);
        g_Weff[idx] = s * 0.125f;
    }
}
__global__ void k_nop() {}

// ---------------- smem layout (bytes) ----------------
#define FR1H 0
#define FR1L 32768
#define FR2H 65536
#define FR2L 98304
#define FR0H 131072
#define FR0L 135168
#define SM_BIAS0 139264
#define SM_BIAS1 139776
#define SM_BIAS2 140288
#define SM_TOTAL 140800

__device__ __forceinline__ void epi_layer(int nt, const float* c, const float* bias, int lane,
                                          uint32_t ah[8][4], uint32_t al[8][4]) {
    float2 b2 = *(const float2*)&bias[nt * 8 + 2 * (lane & 3)];
    float v0 = fmaxf(c[0] + b2.x, 0.f), v1 = fmaxf(c[1] + b2.y, 0.f);
    float v2 = fmaxf(c[2] + b2.x, 0.f), v3 = fmaxf(c[3] + b2.y, 0.f);
    int s = nt >> 1, h2 = (nt & 1) * 2;
    split_pair(v0, v1, ah[s][h2], al[s][h2]);
    split_pair(v2, v3, ah[s][h2 + 1], al[s][h2 + 1]);
}

__device__ __forceinline__ void reduce_nt(int nt, const float* c, const float* bias, int lane,
                                          int s_first, bool uniform, int ls) {
    float2 b2 = *(const float2*)&bias[nt * 8 + 2 * (lane & 3)];
    float v0 = fmaxf(c[0] + b2.x, 0.f), v1 = fmaxf(c[1] + b2.y, 0.f);
    float v2 = fmaxf(c[2] + b2.x, 0.f), v3 = fmaxf(c[3] + b2.y, 0.f);
    int d0 = nt * 8 + 2 * (lane & 3);
    if (uniform) {
        if (s_first < 0) return;
        float s0 = v0 + v2, s1 = v1 + v3;
        #pragma unroll
        for (int o = 4; o < 32; o <<= 1) {
            s0 += __shfl_xor_sync(0xffffffffu, s0, o);
            s1 += __shfl_xor_sync(0xffffffffu, s1, o);
        }
        if (lane < 4) {
            atomicAdd(&g_seg_sum[s_first * WID + d0], s0);
            atomicAdd(&g_seg_sum[s_first * WID + d0 + 1], s1);
        }
    } else {
        float a0 = 0.f, a1 = 0.f; int cur = -2;
        #pragma unroll 1
        for (int p = 0; p < 16; p++) {
            int src = ((p & 7) << 2) | (lane & 3);
            float t0 = __shfl_sync(0xffffffffu, (p < 8) ? v0 : v2, src);
            float t1 = __shfl_sync(0xffffffffu, (p < 8) ? v1 : v3, src);
            int sp = __shfl_sync(0xffffffffu, ls, p);
            if (sp != cur) {
                if (cur >= 0 && lane < 4) {
                    atomicAdd(&g_seg_sum[cur * WID + d0], a0);
                    atomicAdd(&g_seg_sum[cur * WID + d0 + 1], a1);
                }
                cur = sp; a0 = t0; a1 = t1;
            } else { a0 += t0; a1 += t1; }
        }
        if (cur >= 0 && lane < 4) {
            atomicAdd(&g_seg_sum[cur * WID + d0], a0);
            atomicAdd(&g_seg_sum[cur * WID + d0 + 1], a1);
        }
    }
}

// ---------------- K2: barrier-free warp-independent MLP, 12 warps/SM ----------------
__global__ void __launch_bounds__(MLP_THREADS, 1)
k_mlp(const float* __restrict__ in, const int* __restrict__ seg,
      const float* __restrict__ W0, const float* __restrict__ b0,
      const float* __restrict__ W1, const float* __restrict__ b1,
      const float* __restrict__ Wl, const float* __restrict__ bl,
      int n)
{
    extern __shared__ char smc[];
    float* sbias0 = (float*)(smc + SM_BIAS0);
    float* sbias1 = (float*)(smc + SM_BIAS1);
    float* sbias2 = (float*)(smc + SM_BIAS2);

    int t = threadIdx.x;
    int lane = t & 31;
    int w = t >> 5;

    // ---- stage weights into B-fragment order (hi/lo split) ----
    for (int item = t; item < 8704; item += MLP_THREADS) {
        int l, rem;
        if (item < 512) { l = 0; rem = item; }
        else if (item < 4608) { l = 1; rem = item - 512; }
        else { l = 2; rem = item - 4608; }
        int lane_ = rem & 31;
        int ksnt = rem >> 5;
        int ks = (l == 0) ? 0 : (ksnt & 7);
        int nt = (l == 0) ? ksnt : (ksnt >> 3);
        int nn = nt * 8 + (lane_ >> 2);
        int k0 = ks * 16 + (lane_ & 3) * 2;
        const float* W = (l == 0) ? W0 : (l == 1) ? W1 : Wl;
        float w00 = W[k0 * WID + nn];
        float w01 = W[(k0 + 1) * WID + nn];
        float w08 = W[(k0 + 8) * WID + nn];
        float w09 = W[(k0 + 9) * WID + nn];
        uint32_t hx, lx, hy, ly;
        split_pair(w00, w01, hx, lx);
        split_pair(w08, w09, hy, ly);
        int hb = (l == 0) ? FR0H : (l == 1) ? FR1H : FR2H;
        int lb = (l == 0) ? FR0L : (l == 1) ? FR1L : FR2L;
        int entry = (l == 0) ? (nt * 32 + lane_) : ((nt * 8 + ks) * 32 + lane_);
        ((uint2*)(smc + hb))[entry] = make_uint2(hx, hy);
        ((uint2*)(smc + lb))[entry] = make_uint2(lx, ly);
    }
    if (t < WID) { sbias0[t] = b0[t]; sbias1[t] = b1[t]; sbias2[t] = bl[t]; }
    __syncthreads();   // the only barrier

    const uint2* f0h = (const uint2*)(smc + FR0H);
    const uint2* f0l = (const uint2*)(smc + FR0L);
    const uint2* f1h = (const uint2*)(smc + FR1H);
    const uint2* f1l = (const uint2*)(smc + FR1L);
    const uint2* f2h = (const uint2*)(smc + FR2H);
    const uint2* f2l = (const uint2*)(smc + FR2L);

    int r = lane >> 2;
    int c2 = (lane & 3) * 2;

    int nwt = (n + 15) >> 4;
    int gw = blockIdx.x * (MLP_THREADS / 32) + w;
    int gstride = gridDim.x * (MLP_THREADS / 32);

    for (int wt = gw; wt < nwt; wt += gstride) {
        int base = wt << 4;

        int ls = -1;
        if (lane < 16 && base + lane < n) ls = __ldg(&seg[base + lane]);
        int s_first = __shfl_sync(0xffffffffu, ls, 0);
        int s_last  = __shfl_sync(0xffffffffu, ls, 15);
        bool uniform = (s_first == s_last);

        // ---- layer-0 A fragments straight from GMEM ----
        int p0 = base + r, p1 = p0 + 8;
        uint32_t a0h[4], a0l[4];
        {
            float2 z = make_float2(0.f, 0.f);
            float2 x00 = (p0 < n) ? *(const float2*)&in[(size_t)p0 * DIN + c2]     : z;
            float2 x01 = (p1 < n) ? *(const float2*)&in[(size_t)p1 * DIN + c2]     : z;
            float2 x80 = (p0 < n) ? *(const float2*)&in[(size_t)p0 * DIN + c2 + 8] : z;
            float2 x81 = (p1 < n) ? *(const float2*)&in[(size_t)p1 * DIN + c2 + 8] : z;
            split_pair(x00.x, x00.y, a0h[0], a0l[0]);
            split_pair(x01.x, x01.y, a0h[1], a0l[1]);
            split_pair(x80.x, x80.y, a0h[2], a0l[2]);
            split_pair(x81.x, x81.y, a0h[3], a0l[3]);
        }

        uint32_t a1h[8][4], a1l[8][4];
        uint32_t a2h[8][4], a2l[8][4];

        // ---- layer 0: K=16 ----
        #pragma unroll
        for (int q = 0; q < 4; q++) {
            float c[4][4] = {};
            uint2 bh[4], blw[4];
            #pragma unroll
            for (int j = 0; j < 4; j++) {
                int nt = q * 4 + j;
                bh[j]  = f0h[nt * 32 + lane];
                blw[j] = f0l[nt * 32 + lane];
            }
            #pragma unroll
            for (int j = 0; j < 4; j++) mma16816(c[j], a0h, bh[j].x, bh[j].y);
            #pragma unroll
            for (int j = 0; j < 4; j++) mma16816(c[j], a0l, bh[j].x, bh[j].y);
            #pragma unroll
            for (int j = 0; j < 4; j++) mma16816(c[j], a0h, blw[j].x, blw[j].y);
            #pragma unroll
            for (int j = 0; j < 4; j++) epi_layer(q * 4 + j, c[j], sbias0, lane, a1h, a1l);
        }

        // ---- layer 1: K=128 ----
        #pragma unroll
        for (int q = 0; q < 4; q++) {
            float c[4][4] = {};
            #pragma unroll
            for (int ks = 0; ks < 8; ks++) {
                uint2 bh[4], blw[4];
                #pragma unroll
                for (int j = 0; j < 4; j++) {
                    int nt = q * 4 + j;
                    bh[j]  = f1h[(nt * 8 + ks) * 32 + lane];
                    blw[j] = f1l[(nt * 8 + ks) * 32 + lane];
                }
                #pragma unroll
                for (int j = 0; j < 4; j++) mma16816(c[j], a1h[ks], bh[j].x, bh[j].y);
                #pragma unroll
                for (int j = 0; j < 4; j++) mma16816(c[j], a1l[ks], bh[j].x, bh[j].y);
                #pragma unroll
                for (int j = 0; j < 4; j++) mma16816(c[j], a1h[ks], blw[j].x, blw[j].y);
            }
            #pragma unroll
            for (int j = 0; j < 4; j++) epi_layer(q * 4 + j, c[j], sbias1, lane, a2h, a2l);
        }

        // ---- layer 2: K=128, fused segment reduction ----
        #pragma unroll
        for (int q = 0; q < 4; q++) {
            float c[4][4] = {};
            #pragma unroll
            for (int ks = 0; ks < 8; ks++) {
                uint2 bh[4], blw[4];
                #pragma unroll
                for (int j = 0; j < 4; j++) {
                    int nt = q * 4 + j;
                    bh[j]  = f2h[(nt * 8 + ks) * 32 + lane];
                    blw[j] = f2l[(nt * 8 + ks) * 32 + lane];
                }
                #pragma unroll
                for (int j = 0; j < 4; j++) mma16816(c[j], a2h[ks], bh[j].x, bh[j].y);
                #pragma unroll
                for (int j = 0; j < 4; j++) mma16816(c[j], a2l[ks], bh[j].x, bh[j].y);
                #pragma unroll
                for (int j = 0; j < 4; j++) mma16816(c[j], a2h[ks], blw[j].x, blw[j].y);
            }
            #pragma unroll
            for (int j = 0; j < 4; j++)
                reduce_nt(q * 4 + j, c[j], sbias2, lane, s_first, uniform, ls);
        }
    }
}

// ---------------- K3: agg + seg_head (R5 version) ----------------
__global__ void k_agg(const float* __restrict__ Wrho, const float* __restrict__ brho,
                      const int* __restrict__ seg, int n) {
    __shared__ float m[WID];
    __shared__ float a[WID];
    __shared__ int bnd[2];
    int s = blockIdx.x;
    int j = threadIdx.x;
    if (j < 2) {
        int key = s + j;
        int lo = 0, hi = n;
        while (lo < hi) { int mid = (lo + hi) >> 1; if (seg[mid] < key) lo = mid + 1; else hi = mid; }
        bnd[j] = lo;
    }
    __syncthreads();
    float cnt = fmaxf((float)(bnd[1] - bnd[0]), 1.f);
    m[j] = g_seg_sum[s * WID + j] / cnt;
    __syncthreads();
    float acc = brho[j];
    #pragma unroll 8
    for (int k = 0; k < WID; k++) acc = fmaf(m[k], Wrho[k * WID + j], acc);
    a[j] = fmaxf(acc, 0.f);
    __syncthreads();
    if (j < HEADS) {
        float sh = 0.f;
        #pragma unroll 8
        for (int k = 0; k < WID; k++) sh = fmaf(a[k], g_Weff[(DIN + k) * HEADS + j], sh);
        g_seg_head[s * HEADS + j] = sh;
    }
}

// ---------------- K4: per-segment softmax, register-resident pre ----------------
#define SMX_THREADS 256
__global__ void k_softmax(const float* __restrict__ in, const int* __restrict__ seg,
                          float* __restrict__ out, int n)
{
    __shared__ int s_lo, s_hi;
    __shared__ float sWe[DIN * HEADS];
    __shared__ float red[8 * HEADS];
    __shared__ float s_stat[HEADS];

    int s = blockIdx.x;
    int t = threadIdx.x;
    if (t == 0) {
        int lo = 0, hi = n;
        while (lo < hi) { int mid = (lo + hi) >> 1; if (seg[mid] < s) lo = mid + 1; else hi = mid; }
        s_lo = lo;
    }
    if (t == 1) {
        int lo = 0, hi = n;
        while (lo < hi) { int mid = (lo + hi) >> 1; if (seg[mid] < s + 1) lo = mid + 1; else hi = mid; }
        s_hi = lo;
    }
    if (t < DIN * HEADS) sWe[t] = g_Weff[t];
    __syncthreads();

    int lo = s_lo, hi = s_hi;
    int cnt = hi - lo;
    if (cnt <= 0) return;

    float shead[HEADS];
    #pragma unroll
    for (int h = 0; h < HEADS; h++) shead[h] = g_seg_head[s * HEADS + h];

    int wid = t >> 5, lid = t & 31;
    bool incore = (cnt <= 4 * SMX_THREADS);

    float prc[4][HEADS];
    float mx[HEADS] = {-1e30f, -1e30f, -1e30f, -1e30f};

    if (incore) {
        #pragma unroll
        for (int it = 0; it < 4; it++) {
            int i = lo + t + it * SMX_THREADS;
            if (i < hi) {
                float xv[DIN];
                #pragma unroll
                for (int q = 0; q < 4; q++)
                    *(float4*)&xv[q * 4] = *(const float4*)&in[(size_t)i * DIN + q * 4];
                #pragma unroll
                for (int h = 0; h < HEADS; h++) {
                    float p = shead[h];
                    #pragma unroll
                    for (int k = 0; k < DIN; k++) p = fmaf(xv[k], sWe[k * HEADS + h], p);
                    prc[it][h] = p;
                    mx[h] = fmaxf(mx[h], p);
                }
            } else {
                #pragma unroll
                for (int h = 0; h < HEADS; h++) prc[it][h] = -1e30f;
            }
        }
    } else {
        for (int i = lo + t; i < hi; i += SMX_THREADS) {
            float xv[DIN];
            #pragma unroll
            for (int q = 0; q < 4; q++)
                *(float4*)&xv[q * 4] = *(const float4*)&in[(size_t)i * DIN + q * 4];
            #pragma unroll
            for (int h = 0; h < HEADS; h++) {
                float p = shead[h];
                #pragma unroll
                for (int k = 0; k < DIN; k++) p = fmaf(xv[k], sWe[k * HEADS + h], p);
                g_pre[(size_t)i * HEADS + h] = p;
                mx[h] = fmaxf(mx[h], p);
            }
        }
    }
    #pragma unroll
    for (int h = 0; h < HEADS; h++)
        for (int o = 16; o; o >>= 1) mx[h] = fmaxf(mx[h], __shfl_xor_sync(0xffffffffu, mx[h], o));
    if (lid == 0)
        #pragma unroll
        for (int h = 0; h < HEADS; h++) red[wid * HEADS + h] = mx[h];
    __syncthreads();
    if (t < HEADS) {
        float v = red[t];
        for (int w = 1; w < 8; w++) v = fmaxf(v, red[w * HEADS + t]);
        s_stat[t] = v;
    }
    __syncthreads();
    float gmax[HEADS];
    #pragma unroll
    for (int h = 0; h < HEADS; h++) gmax[h] = s_stat[h];
    __syncthreads();

    float sum[HEADS] = {0.f, 0.f, 0.f, 0.f};
    if (incore) {
        #pragma unroll
        for (int it = 0; it < 4; it++) {
            int i = lo + t + it * SMX_THREADS;
            if (i < hi) {
                #pragma unroll
                for (int h = 0; h < HEADS; h++) {
                    float e = expf(prc[it][h] - gmax[h]);
                    prc[it][h] = e;
                    sum[h] += e;
                }
            }
        }
    } else {
        for (int i = lo + t; i < hi; i += SMX_THREADS) {
            #pragma unroll
            for (int h = 0; h < HEADS; h++) {
                float e = expf(g_pre[(size_t)i * HEADS + h] - gmax[h]);
                g_pre[(size_t)i * HEADS + h] = e;
                sum[h] += e;
            }
        }
    }
    #pragma unroll
    for (int h = 0; h < HEADS; h++)
        for (int o = 16; o; o >>= 1) sum[h] += __shfl_xor_sync(0xffffffffu, sum[h], o);
    if (lid == 0)
        #pragma unroll
        for (int h = 0; h < HEADS; h++) red[wid * HEADS + h] = sum[h];
    __syncthreads();
    if (t < HEADS) {
        float v = 0.f;
        for (int w = 0; w < 8; w++) v += red[w * HEADS + t];
        s_stat[t] = v;
    }
    __syncthreads();
    float inv[HEADS];
    #pragma unroll
    for (int h = 0; h < HEADS; h++) inv[h] = 1.0f / s_stat[h];

    if (incore) {
        #pragma unroll
        for (int it = 0; it < 4; it++) {
            int i = lo + t + it * SMX_THREADS;
            if (i < hi) {
                float4 o;
                o.x = prc[it][0] * inv[0];
                o.y = prc[it][1] * inv[1];
                o.z = prc[it][2] * inv[2];
                o.w = prc[it][3] * inv[3];
                *(float4*)&out[(size_t)i * HEADS] = o;
            }
        }
    } else {
        for (int i = lo + t; i < hi; i += SMX_THREADS) {
            #pragma unroll
            for (int h = 0; h < HEADS; h++)
                out[(size_t)i * HEADS + h] = g_pre[(size_t)i * HEADS + h] * inv[h];
        }
    }
}

// ---------------- launch ----------------
extern "C" void kernel_launch(void* const* d_in, const int* in_sizes, int n_in,
                              void* d_out, int out_size)
{
    const float* inputs = (const float*)d_in[0];
    const int*   seg    = (const int*)d_in[1];
    const float* W0 = (const float*)d_in[3];
    const float* b0 = (const float*)d_in[4];
    const float* W1 = (const float*)d_in[5];
    const float* b1 = (const float*)d_in[6];
    const float* Wl = (const float*)d_in[7];
    const float* bl = (const float*)d_in[8];
    const float* Wr = (const float*)d_in[9];
    const float* br = (const float*)d_in[10];
    const float* Wk = (const float*)d_in[11];
    const float* Wq = (const float*)d_in[12];
    float* out = (float*)d_out;

    int n = in_sizes[0] / DIN;

    k_zero<<<(NSEG * WID + 255) / 256, 256>>>();
    k_weff<<<1, 256>>>(Wk, Wq);
    k_nop<<<1, 32>>>();   // keeps k_mlp in ncu capture slot

    cudaFuncSetAttribute(k_mlp, cudaFuncAttributeMaxDynamicSharedMemorySize, SM_TOTAL);
    k_mlp<<<152, MLP_THREADS, SM_TOTAL>>>(inputs, seg, W0, b0, W1, b1, Wl, bl, n);

    k_agg<<<NSEG, WID>>>(Wr, br, seg, n);
    k_softmax<<<NSEG, SMX_THREADS>>>(inputs, seg, out, n);
}

// round 8
// speedup vs baseline: 1.4624x; 1.2478x over previous
#include <cuda_runtime.h>
#include <cuda_bf16.h>
#include <math.h>
#include <stdint.h>

#define NPTS_MAX 500000
#define NSEG 1024
#define DIN 16
#define WID 128
#define HEADS 4
#define DOT 64
#define COMB 144
#define MLP_THREADS 512

// ---------------- device scratch ----------------
__device__ float g_seg_sum[NSEG * WID];
__device__ float g_seg_head[NSEG * HEADS];
__device__ float g_Weff[COMB * HEADS];
__device__ float g_pre[NPTS_MAX * HEADS];   // softmax fallback only

// ---------------- helpers ----------------
__device__ __forceinline__ uint32_t pack_bf2(float lo, float hi) {
    uint32_t r;
    asm("cvt.rn.bf16x2.f32 %0, %1, %2;" : "=r"(r) : "f"(hi), "f"(lo));
    return r;
}
// weights: split into bf16 hi (rn) + bf16 residual
__device__ __forceinline__ void wsplit_pair(float v0, float v1, uint32_t& hw, uint32_t& lw) {
    __nv_bfloat16 h0 = __float2bfloat16(v0);
    __nv_bfloat16 h1 = __float2bfloat16(v1);
    hw = ((uint32_t)__bfloat16_as_ushort(h1) << 16) | __bfloat16_as_ushort(h0);
    lw = pack_bf2(v0 - __bfloat162float(h0), v1 - __bfloat162float(h1));
}
__device__ __forceinline__ void mma16816(float* c, const uint32_t* a, uint32_t b0, uint32_t b1) {
    asm volatile(
        "mma.sync.aligned.m16n8k16.row.col.f32.bf16.bf16.f32 "
        "{%0,%1,%2,%3}, {%4,%5,%6,%7}, {%8,%9}, {%0,%1,%2,%3};"
        : "+f"(c[0]), "+f"(c[1]), "+f"(c[2]), "+f"(c[3])
        : "r"(a[0]), "r"(a[1]), "r"(a[2]), "r"(a[3]), "r"(b0), "r"(b1));
}

// ---------------- K0 / K1 / dummy ----------------
__global__ void k_zero() {
    int i = blockIdx.x * blockDim.x + threadIdx.x;
    if (i < NSEG * WID) g_seg_sum[i] = 0.f;
}
__global__ void k_weff(const float* __restrict__ Wk, const float* __restrict__ Wq) {
    int t = threadIdx.x;
    for (int idx = t; idx < COMB * HEADS; idx += 256) {
        int i = idx >> 2, h = idx & 3;
        float s = 0.f;
        #pragma unroll 8
        for (int d = 0; d < DOT; d++)
            s = fmaf(Wk[i * (DOT * HEADS) + h * DOT + d], Wq[h * DOT + d], s);
        g_Weff[idx] = s * 0.125f;
    }
}
__global__ void k_nop() {}

// ---------------- smem layout (bytes) ----------------
#define FR1H 0
#define FR1L 32768
#define FR2H 65536
#define FR2L 98304
#define FR0H 131072
#define FR0L 135168
#define SM_BIAS0 139264
#define SM_BIAS1 139776
#define SM_BIAS2 140288
#define SM_TOTAL 140800

// epilogue: relu(C+bias) -> bf16(rn) A-fragments for next layer
__device__ __forceinline__ void epi_layer(int nt, const float* c, const float* bias, int lane,
                                          uint32_t ah[8][4]) {
    float2 b2 = *(const float2*)&bias[nt * 8 + 2 * (lane & 3)];
    float v0 = fmaxf(c[0] + b2.x, 0.f), v1 = fmaxf(c[1] + b2.y, 0.f);
    float v2 = fmaxf(c[2] + b2.x, 0.f), v3 = fmaxf(c[3] + b2.y, 0.f);
    int s = nt >> 1, h2 = (nt & 1) * 2;
    ah[s][h2]     = pack_bf2(v0, v1);
    ah[s][h2 + 1] = pack_bf2(v2, v3);
}

__device__ __forceinline__ void reduce_nt(int nt, const float* c, const float* bias, int lane,
                                          int s_first, bool uniform, int ls) {
    float2 b2 = *(const float2*)&bias[nt * 8 + 2 * (lane & 3)];
    float v0 = fmaxf(c[0] + b2.x, 0.f), v1 = fmaxf(c[1] + b2.y, 0.f);
    float v2 = fmaxf(c[2] + b2.x, 0.f), v3 = fmaxf(c[3] + b2.y, 0.f);
    int d0 = nt * 8 + 2 * (lane & 3);
    if (uniform) {
        if (s_first < 0) return;
        float s0 = v0 + v2, s1 = v1 + v3;
        #pragma unroll
        for (int o = 4; o < 32; o <<= 1) {
            s0 += __shfl_xor_sync(0xffffffffu, s0, o);
            s1 += __shfl_xor_sync(0xffffffffu, s1, o);
        }
        if (lane < 4) {
            atomicAdd(&g_seg_sum[s_first * WID + d0], s0);
            atomicAdd(&g_seg_sum[s_first * WID + d0 + 1], s1);
        }
    } else {
        float a0 = 0.f, a1 = 0.f; int cur = -2;
        #pragma unroll 1
        for (int p = 0; p < 16; p++) {
            int src = ((p & 7) << 2) | (lane & 3);
            float t0 = __shfl_sync(0xffffffffu, (p < 8) ? v0 : v2, src);
            float t1 = __shfl_sync(0xffffffffu, (p < 8) ? v1 : v3, src);
            int sp = __shfl_sync(0xffffffffu, ls, p);
            if (sp != cur) {
                if (cur >= 0 && lane < 4) {
                    atomicAdd(&g_seg_sum[cur * WID + d0], a0);
                    atomicAdd(&g_seg_sum[cur * WID + d0 + 1], a1);
                }
                cur = sp; a0 = t0; a1 = t1;
            } else { a0 += t0; a1 += t1; }
        }
        if (cur >= 0 && lane < 4) {
            atomicAdd(&g_seg_sum[cur * WID + d0], a0);
            atomicAdd(&g_seg_sum[cur * WID + d0 + 1], a1);
        }
    }
}

// ---------------- K2: barrier-free warp-independent MLP, 16 warps, 2-pass ----------------
__global__ void __launch_bounds__(MLP_THREADS, 1)
k_mlp(const float* __restrict__ in, const int* __restrict__ seg,
      const float* __restrict__ W0, const float* __restrict__ b0,
      const float* __restrict__ W1, const float* __restrict__ b1,
      const float* __restrict__ Wl, const float* __restrict__ bl,
      int n)
{
    extern __shared__ char smc[];
    float* sbias0 = (float*)(smc + SM_BIAS0);
    float* sbias1 = (float*)(smc + SM_BIAS1);
    float* sbias2 = (float*)(smc + SM_BIAS2);

    int t = threadIdx.x;
    int lane = t & 31;
    int w = t >> 5;

    // ---- stage weights into B-fragment order (hi/lo split) ----
    for (int item = t; item < 8704; item += MLP_THREADS) {
        int l, rem;
        if (item < 512) { l = 0; rem = item; }
        else if (item < 4608) { l = 1; rem = item - 512; }
        else { l = 2; rem = item - 4608; }
        int lane_ = rem & 31;
        int ksnt = rem >> 5;
        int ks = (l == 0) ? 0 : (ksnt & 7);
        int nt = (l == 0) ? ksnt : (ksnt >> 3);
        int nn = nt * 8 + (lane_ >> 2);
        int k0 = ks * 16 + (lane_ & 3) * 2;
        const float* W = (l == 0) ? W0 : (l == 1) ? W1 : Wl;
        float w00 = W[k0 * WID + nn];
        float w01 = W[(k0 + 1) * WID + nn];
        float w08 = W[(k0 + 8) * WID + nn];
        float w09 = W[(k0 + 9) * WID + nn];
        uint32_t hx, lx, hy, ly;
        wsplit_pair(w00, w01, hx, lx);
        wsplit_pair(w08, w09, hy, ly);
        int hb = (l == 0) ? FR0H : (l == 1) ? FR1H : FR2H;
        int lb = (l == 0) ? FR0L : (l == 1) ? FR1L : FR2L;
        int entry = (l == 0) ? (nt * 32 + lane_) : ((nt * 8 + ks) * 32 + lane_);
        ((uint2*)(smc + hb))[entry] = make_uint2(hx, hy);
        ((uint2*)(smc + lb))[entry] = make_uint2(lx, ly);
    }
    if (t < WID) { sbias0[t] = b0[t]; sbias1[t] = b1[t]; sbias2[t] = bl[t]; }
    __syncthreads();   // the only barrier

    const uint2* f0h = (const uint2*)(smc + FR0H);
    const uint2* f0l = (const uint2*)(smc + FR0L);
    const uint2* f1h = (const uint2*)(smc + FR1H);
    const uint2* f1l = (const uint2*)(smc + FR1L);
    const uint2* f2h = (const uint2*)(smc + FR2H);
    const uint2* f2l = (const uint2*)(smc + FR2L);

    int r = lane >> 2;
    int c2 = (lane & 3) * 2;

    int nwt = (n + 15) >> 4;
    int gw = blockIdx.x * (MLP_THREADS / 32) + w;
    int gstride = gridDim.x * (MLP_THREADS / 32);

    for (int wt = gw; wt < nwt; wt += gstride) {
        int base = wt << 4;

        int ls = -1;
        if (lane < 16 && base + lane < n) ls = __ldg(&seg[base + lane]);
        int s_first = __shfl_sync(0xffffffffu, ls, 0);
        int s_last  = __shfl_sync(0xffffffffu, ls, 15);
        bool uniform = (s_first == s_last);

        // ---- layer-0 A fragments straight from GMEM (bf16 rn) ----
        int p0 = base + r, p1 = p0 + 8;
        uint32_t a0h[4];
        {
            float2 z = make_float2(0.f, 0.f);
            float2 x00 = (p0 < n) ? *(const float2*)&in[(size_t)p0 * DIN + c2]     : z;
            float2 x01 = (p1 < n) ? *(const float2*)&in[(size_t)p1 * DIN + c2]     : z;
            float2 x80 = (p0 < n) ? *(const float2*)&in[(size_t)p0 * DIN + c2 + 8] : z;
            float2 x81 = (p1 < n) ? *(const float2*)&in[(size_t)p1 * DIN + c2 + 8] : z;
            a0h[0] = pack_bf2(x00.x, x00.y);
            a0h[1] = pack_bf2(x01.x, x01.y);
            a0h[2] = pack_bf2(x80.x, x80.y);
            a0h[3] = pack_bf2(x81.x, x81.y);
        }

        uint32_t a1h[8][4];
        uint32_t a2h[8][4];

        // ---- layer 0: K=16, 2-pass (hiW + loW) ----
        #pragma unroll
        for (int q = 0; q < 4; q++) {
            float c[4][4] = {};
            uint2 bh[4], blw[4];
            #pragma unroll
            for (int j = 0; j < 4; j++) {
                int nt = q * 4 + j;
                bh[j]  = f0h[nt * 32 + lane];
                blw[j] = f0l[nt * 32 + lane];
            }
            #pragma unroll
            for (int j = 0; j < 4; j++) mma16816(c[j], a0h, bh[j].x, bh[j].y);
            #pragma unroll
            for (int j = 0; j < 4; j++) mma16816(c[j], a0h, blw[j].x, blw[j].y);
            #pragma unroll
            for (int j = 0; j < 4; j++) epi_layer(q * 4 + j, c[j], sbias0, lane, a1h);
        }

        // ---- layer 1: K=128, 2-pass ----
        #pragma unroll
        for (int q = 0; q < 4; q++) {
            float c[4][4] = {};
            #pragma unroll
            for (int ks = 0; ks < 8; ks++) {
                uint2 bh[4], blw[4];
                #pragma unroll
                for (int j = 0; j < 4; j++) {
                    int nt = q * 4 + j;
                    bh[j]  = f1h[(nt * 8 + ks) * 32 + lane];
                    blw[j] = f1l[(nt * 8 + ks) * 32 + lane];
                }
                #pragma unroll
                for (int j = 0; j < 4; j++) mma16816(c[j], a1h[ks], bh[j].x, bh[j].y);
                #pragma unroll
                for (int j = 0; j < 4; j++) mma16816(c[j], a1h[ks], blw[j].x, blw[j].y);
            }
            #pragma unroll
            for (int j = 0; j < 4; j++) epi_layer(q * 4 + j, c[j], sbias1, lane, a2h);
        }

        // ---- layer 2: K=128, 2-pass, fused segment reduction ----
        #pragma unroll
        for (int q = 0; q < 4; q++) {
            float c[4][4] = {};
            #pragma unroll
            for (int ks = 0; ks < 8; ks++) {
                uint2 bh[4], blw[4];
                #pragma unroll
                for (int j = 0; j < 4; j++) {
                    int nt = q * 4 + j;
                    bh[j]  = f2h[(nt * 8 + ks) * 32 + lane];
                    blw[j] = f2l[(nt * 8 + ks) * 32 + lane];
                }
                #pragma unroll
                for (int j = 0; j < 4; j++) mma16816(c[j], a2h[ks], bh[j].x, bh[j].y);
                #pragma unroll
                for (int j = 0; j < 4; j++) mma16816(c[j], a2h[ks], blw[j].x, blw[j].y);
            }
            #pragma unroll
            for (int j = 0; j < 4; j++)
                reduce_nt(q * 4 + j, c[j], sbias2, lane, s_first, uniform, ls);
        }
    }
}

// ---------------- K3: agg + seg_head ----------------
__global__ void k_agg(const float* __restrict__ Wrho, const float* __restrict__ brho,
                      const int* __restrict__ seg, int n) {
    __shared__ float m[WID];
    __shared__ float a[WID];
    __shared__ int bnd[2];
    int s = blockIdx.x;
    int j = threadIdx.x;
    if (j < 2) {
        int key = s + j;
        int lo = 0, hi = n;
        while (lo < hi) { int mid = (lo + hi) >> 1; if (seg[mid] < key) lo = mid + 1; else hi = mid; }
        bnd[j] = lo;
    }
    __syncthreads();
    float cnt = fmaxf((float)(bnd[1] - bnd[0]), 1.f);
    m[j] = g_seg_sum[s * WID + j] / cnt;
    __syncthreads();
    float acc = brho[j];
    #pragma unroll 8
    for (int k = 0; k < WID; k++) acc = fmaf(m[k], Wrho[k * WID + j], acc);
    a[j] = fmaxf(acc, 0.f);
    __syncthreads();
    if (j < HEADS) {
        float sh = 0.f;
        #pragma unroll 8
        for (int k = 0; k < WID; k++) sh = fmaf(a[k], g_Weff[(DIN + k) * HEADS + j], sh);
        g_seg_head[s * HEADS + j] = sh;
    }
}

// ---------------- K4: per-segment softmax, register-resident pre ----------------
#define SMX_THREADS 256
__global__ void k_softmax(const float* __restrict__ in, const int* __restrict__ seg,
                          float* __restrict__ out, int n)
{
    __shared__ int s_lo, s_hi;
    __shared__ float sWe[DIN * HEADS];
    __shared__ float red[8 * HEADS];
    __shared__ float s_stat[HEADS];

    int s = blockIdx.x;
    int t = threadIdx.x;
    if (t == 0) {
        int lo = 0, hi = n;
        while (lo < hi) { int mid = (lo + hi) >> 1; if (seg[mid] < s) lo = mid + 1; else hi = mid; }
        s_lo = lo;
    }
    if (t == 1) {
        int lo = 0, hi = n;
        while (lo < hi) { int mid = (lo + hi) >> 1; if (seg[mid] < s + 1) lo = mid + 1; else hi = mid; }
        s_hi = lo;
    }
    if (t < DIN * HEADS) sWe[t] = g_Weff[t];
    __syncthreads();

    int lo = s_lo, hi = s_hi;
    int cnt = hi - lo;
    if (cnt <= 0) return;

    float shead[HEADS];
    #pragma unroll
    for (int h = 0; h < HEADS; h++) shead[h] = g_seg_head[s * HEADS + h];

    int wid = t >> 5, lid = t & 31;
    bool incore = (cnt <= 4 * SMX_THREADS);

    float prc[4][HEADS];
    float mx[HEADS] = {-1e30f, -1e30f, -1e30f, -1e30f};

    if (incore) {
        #pragma unroll
        for (int it = 0; it < 4; it++) {
            int i = lo + t + it * SMX_THREADS;
            if (i < hi) {
                float xv[DIN];
                #pragma unroll
                for (int q = 0; q < 4; q++)
                    *(float4*)&xv[q * 4] = *(const float4*)&in[(size_t)i * DIN + q * 4];
                #pragma unroll
                for (int h = 0; h < HEADS; h++) {
                    float p = shead[h];
                    #pragma unroll
                    for (int k = 0; k < DIN; k++) p = fmaf(xv[k], sWe[k * HEADS + h], p);
                    prc[it][h] = p;
                    mx[h] = fmaxf(mx[h], p);
                }
            } else {
                #pragma unroll
                for (int h = 0; h < HEADS; h++) prc[it][h] = -1e30f;
            }
        }
    } else {
        for (int i = lo + t; i < hi; i += SMX_THREADS) {
            float xv[DIN];
            #pragma unroll
            for (int q = 0; q < 4; q++)
                *(float4*)&xv[q * 4] = *(const float4*)&in[(size_t)i * DIN + q * 4];
            #pragma unroll
            for (int h = 0; h < HEADS; h++) {
                float p = shead[h];
                #pragma unroll
                for (int k = 0; k < DIN; k++) p = fmaf(xv[k], sWe[k * HEADS + h], p);
                g_pre[(size_t)i * HEADS + h] = p;
                mx[h] = fmaxf(mx[h], p);
            }
        }
    }
    #pragma unroll
    for (int h = 0; h < HEADS; h++)
        for (int o = 16; o; o >>= 1) mx[h] = fmaxf(mx[h], __shfl_xor_sync(0xffffffffu, mx[h], o));
    if (lid == 0)
        #pragma unroll
        for (int h = 0; h < HEADS; h++) red[wid * HEADS + h] = mx[h];
    __syncthreads();
    if (t < HEADS) {
        float v = red[t];
        for (int w = 1; w < 8; w++) v = fmaxf(v, red[w * HEADS + t]);
        s_stat[t] = v;
    }
    __syncthreads();
    float gmax[HEADS];
    #pragma unroll
    for (int h = 0; h < HEADS; h++) gmax[h] = s_stat[h];
    __syncthreads();

    float sum[HEADS] = {0.f, 0.f, 0.f, 0.f};
    if (incore) {
        #pragma unroll
        for (int it = 0; it < 4; it++) {
            int i = lo + t + it * SMX_THREADS;
            if (i < hi) {
                #pragma unroll
                for (int h = 0; h < HEADS; h++) {
                    float e = expf(prc[it][h] - gmax[h]);
                    prc[it][h] = e;
                    sum[h] += e;
                }
            }
        }
    } else {
        for (int i = lo + t; i < hi; i += SMX_THREADS) {
            #pragma unroll
            for (int h = 0; h < HEADS; h++) {
                float e = expf(g_pre[(size_t)i * HEADS + h] - gmax[h]);
                g_pre[(size_t)i * HEADS + h] = e;
                sum[h] += e;
            }
        }
    }
    #pragma unroll
    for (int h = 0; h < HEADS; h++)
        for (int o = 16; o; o >>= 1) sum[h] += __shfl_xor_sync(0xffffffffu, sum[h], o);
    if (lid == 0)
        #pragma unroll
        for (int h = 0; h < HEADS; h++) red[wid * HEADS + h] = sum[h];
    __syncthreads();
    if (t < HEADS) {
        float v = 0.f;
        for (int w = 0; w < 8; w++) v += red[w * HEADS + t];
        s_stat[t] = v;
    }
    __syncthreads();
    float inv[HEADS];
    #pragma unroll
    for (int h = 0; h < HEADS; h++) inv[h] = 1.0f / s_stat[h];

    if (incore) {
        #pragma unroll
        for (int it = 0; it < 4; it++) {
            int i = lo + t + it * SMX_THREADS;
            if (i < hi) {
                float4 o;
                o.x = prc[it][0] * inv[0];
                o.y = prc[it][1] * inv[1];
                o.z = prc[it][2] * inv[2];
                o.w = prc[it][3] * inv[3];
                *(float4*)&out[(size_t)i * HEADS] = o;
            }
        }
    } else {
        for (int i = lo + t; i < hi; i += SMX_THREADS) {
            #pragma unroll
            for (int h = 0; h < HEADS; h++)
                out[(size_t)i * HEADS + h] = g_pre[(size_t)i * HEADS + h] * inv[h];
        }
    }
}

// ---------------- launch ----------------
extern "C" void kernel_launch(void* const* d_in, const int* in_sizes, int n_in,
                              void* d_out, int out_size)
{
    const float* inputs = (const float*)d_in[0];
    const int*   seg    = (const int*)d_in[1];
    const float* W0 = (const float*)d_in[3];
    const float* b0 = (const float*)d_in[4];
    const float* W1 = (const float*)d_in[5];
    const float* b1 = (const float*)d_in[6];
    const float* Wl = (const float*)d_in[7];
    const float* bl = (const float*)d_in[8];
    const float* Wr = (const float*)d_in[9];
    const float* br = (const float*)d_in[10];
    const float* Wk = (const float*)d_in[11];
    const float* Wq = (const float*)d_in[12];
    float* out = (float*)d_out;

    int n = in_sizes[0] / DIN;

    k_zero<<<(NSEG * WID + 255) / 256, 256>>>();
    k_weff<<<1, 256>>>(Wk, Wq);
    k_nop<<<1, 32>>>();   // keeps k_mlp in ncu capture slot

    cudaFuncSetAttribute(k_mlp, cudaFuncAttributeMaxDynamicSharedMemorySize, SM_TOTAL);
    k_mlp<<<152, MLP_THREADS, SM_TOTAL>>>(inputs, seg, W0, b0, W1, b1, Wl, bl, n);

    k_agg<<<NSEG, WID>>>(Wr, br, seg, n);
    k_softmax<<<NSEG, SMX_THREADS>>>(inputs, seg, out, n);
}